// round 2
// baseline (speedup 1.0000x reference)
#include <cuda_runtime.h>

#define MAXN 80000
#define KOBJ 512
#define FEPS 1e-9f

// ---------------- scratch (static device globals; no allocation) ----------------
__device__ float4 g_hit[MAXN];                 // x, y, q, x^2+y^2+1e-6
__device__ unsigned long long g_key[KOBJ];     // packed (beta_bits<<32) | ~index
__device__ float g_cnt[KOBJ], g_num[KOBJ], g_den[KOBJ];
__device__ float g_att[KOBJ], g_ro[KOBJ], g_rep[KOBJ];
__device__ float g_mx[KOBJ], g_my[KOBJ], g_c2[KOBJ];
__device__ float g_qa[KOBJ], g_ba[KOBJ], g_xk[KOBJ], g_yk[KOBJ];
__device__ float g_scal[4];                    // noise_beta_sum, noise_cnt, cc_sum

// ---------------- helpers ----------------
__device__ __forceinline__ float asqrtf(float x) {
    float r;
    asm("sqrt.approx.f32 %0, %1;" : "=f"(r) : "f"(x));
    return r;
}

__device__ __forceinline__ float softclipf(float v, float s) {
    float x = v / s;
    if (x > 1.0f) x = logf(x + 1.0f);
    return x * s;
}

// ---------------- kernel 0: zero accumulators ----------------
__global__ void zero_kernel() {
    int k = threadIdx.x;
    g_key[k] = 0ull;
    g_cnt[k] = 0.f; g_num[k] = 0.f; g_den[k] = 0.f;
    g_att[k] = 0.f; g_ro[k]  = 0.f; g_rep[k] = 0.f;
    if (k < 4) g_scal[k] = 0.f;
}

// ---------------- kernel 1: per-hit precompute + per-object atomics ----------------
__global__ void passA_kernel(const float* __restrict__ pbeta, const float* __restrict__ pcc,
                             const float* __restrict__ pen,   const float* __restrict__ ppos,
                             const float* __restrict__ ptime, const float* __restrict__ pid,
                             const int*   __restrict__ tidx,  const float* __restrict__ ten,
                             const float* __restrict__ tpos,  const float* __restrict__ ttime,
                             int N)
{
    int i = blockIdx.x * blockDim.x + threadIdx.x;
    float ccs = 0.f, nb = 0.f, nc = 0.f;
    if (i < N) {
        float b = fminf(fmaxf(pbeta[i], 1e-6f), 1.0f - 1e-6f);
        float a = atanhf(b);
        float q = a * a + 0.1f;
        float x = pcc[2 * i], y = pcc[2 * i + 1];
        ccs = x * x + y * y;
        g_hit[i] = make_float4(x, y, q, ccs + 1e-6f);
        int k = tidx[i];
        if (k < 0) {
            nb = b; nc = 1.f;
        } else {
            atomicAdd(&g_cnt[k], 1.f);
            unsigned long long key =
                ((unsigned long long)__float_as_uint(b) << 32)
                | (unsigned long long)(0xFFFFFFFFu - (unsigned)i);
            atomicMax(&g_key[k], key);

            float tev = ten[i];
            // energy loss (alt form) + softclip(·, 10)
            float ed = fabsf(tev - pen[i]);
            float el = softclipf(10.0f * expf(-0.1f * ed * ed) + 0.01f * ed, 10.0f);
            // position loss: huber(sqrt(d2/100 + 0.01), 10), softclip 3
            float dx = tpos[2 * i]     - ppos[2 * i];
            float dy = tpos[2 * i + 1] - ppos[2 * i + 1];
            float d2 = dx * dx + dy * dy;
            float arg = sqrtf(d2 / 100.0f + 0.01f);
            float hub = (arg < 10.0f) ? arg * arg : 100.0f + 20.0f * (arg - 10.0f);
            float pl = softclipf(hub, 3.0f);
            // timing loss: huber(dt, 2), softclip 6
            float dt  = ttime[i] - ptime[i];
            float adt = fabsf(dt);
            float th = (adt < 2.0f) ? dt * dt : 4.0f + 4.0f * (adt - 2.0f);
            float tl = softclipf(th, 6.0f);
            // classification loss: 1e-8 * mean(pred_id^2)
            float cs = 0.f;
            #pragma unroll
            for (int c = 0; c < 6; c++) { float v = pid[6 * i + c]; cs += v * v; }
            float cl = 1e-8f * (cs * (1.0f / 6.0f));

            float payload = el + pl + tl + cl;
            float w  = (tev > 10.0f) ? 1.0f : fmaxf((tev - 0.5f) * (1.0f / 9.5f), 0.0f);
            float pw = b * w;
            atomicAdd(&g_num[k], payload * pw);
            atomicAdd(&g_den[k], pw);
        }
    }
    // warp-reduce the global scalars
    #pragma unroll
    for (int o = 16; o; o >>= 1) {
        ccs += __shfl_down_sync(0xFFFFFFFFu, ccs, o);
        nb  += __shfl_down_sync(0xFFFFFFFFu, nb,  o);
        nc  += __shfl_down_sync(0xFFFFFFFFu, nc,  o);
    }
    if ((threadIdx.x & 31) == 0) {
        if (ccs != 0.f) atomicAdd(&g_scal[2], ccs);
        if (nc  != 0.f) { atomicAdd(&g_scal[0], nb); atomicAdd(&g_scal[1], nc); }
    }
}

// ---------------- kernel 2: decode alpha per object ----------------
__global__ void passB_kernel() {
    int k = threadIdx.x;
    float mx = 0.f, my = 0.f, c2 = 0.f, qa = 0.f, ba = 0.f, xx = 0.f, yy = 0.f;
    if (g_cnt[k] > 0.f) {
        unsigned long long key = g_key[k];
        unsigned a = 0xFFFFFFFFu - (unsigned)(key & 0xFFFFFFFFull);
        float4 h = g_hit[a];
        xx = h.x; yy = h.y; qa = h.z;
        ba = __uint_as_float((unsigned)(key >> 32));   // clipped beta at alpha
        mx = -2.f * xx; my = -2.f * yy; c2 = xx * xx + yy * yy;
    }
    g_mx[k] = mx; g_my[k] = my; g_c2[k] = c2;
    g_qa[k] = qa; g_ba[k] = ba; g_xk[k] = xx; g_yk[k] = yy;
}

// ---------------- kernel 3: own-object attractive + own repulsion term ----------------
__global__ void passD_kernel(const int* __restrict__ tidx, int N) {
    int i = blockIdx.x * blockDim.x + threadIdx.x;
    if (i >= N) return;
    int k = tidx[i];
    if (k < 0) return;
    float4 h = g_hit[i];
    float dx = h.x - g_xk[k], dy = h.y - g_yk[k];
    float d2 = dx * dx + dy * dy;
    float qa = g_qa[k];
    atomicAdd(&g_att[k], d2 * qa * h.z);
    // IDENTICAL formula to passC so the subtraction cancels systematically
    float u = fmaf(g_mx[k], h.x, fmaf(g_my[k], h.y, h.w + g_c2[k]));
    float r = fmaxf(1.0f - asqrtf(u), 0.0f);   // NaN (u<0) -> 0, same as passC
    atomicAdd(&g_ro[k], r * qa * h.z);
}

// ---------------- kernel 4: the N x K repulsion sweep ----------------
__global__ void __launch_bounds__(128) passC_kernel(int N) {
    int t = threadIdx.x;                       // each thread owns 4 objects
    float mx0 = g_mx[t      ], my0 = g_my[t      ], c20 = g_c2[t      ];
    float mx1 = g_mx[t + 128], my1 = g_my[t + 128], c21 = g_c2[t + 128];
    float mx2 = g_mx[t + 256], my2 = g_my[t + 256], c22 = g_c2[t + 256];
    float mx3 = g_mx[t + 384], my3 = g_my[t + 384], c23 = g_c2[t + 384];

    int per = (N + (int)gridDim.x - 1) / (int)gridDim.x;
    int s = blockIdx.x * per;
    int e = min(N, s + per);

    float a0 = 0.f, a1 = 0.f, a2 = 0.f, a3 = 0.f;
    #pragma unroll 4
    for (int i = s; i < e; ++i) {
        float4 h = __ldg(&g_hit[i]);           // warp-uniform -> L1 broadcast
        float hw = h.w, hx = h.x, hy = h.y, hq = h.z;
        float u0 = fmaf(mx0, hx, fmaf(my0, hy, hw + c20));
        float u1 = fmaf(mx1, hx, fmaf(my1, hy, hw + c21));
        float u2 = fmaf(mx2, hx, fmaf(my2, hy, hw + c22));
        float u3 = fmaf(mx3, hx, fmaf(my3, hy, hw + c23));
        a0 = fmaf(fmaxf(1.0f - asqrtf(u0), 0.0f), hq, a0);
        a1 = fmaf(fmaxf(1.0f - asqrtf(u1), 0.0f), hq, a1);
        a2 = fmaf(fmaxf(1.0f - asqrtf(u2), 0.0f), hq, a2);
        a3 = fmaf(fmaxf(1.0f - asqrtf(u3), 0.0f), hq, a3);
    }
    atomicAdd(&g_rep[t      ], a0);
    atomicAdd(&g_rep[t + 128], a1);
    atomicAdd(&g_rep[t + 256], a2);
    atomicAdd(&g_rep[t + 384], a3);
}

// ---------------- kernel 5: per-object normalization + final reduction ----------------
__global__ void final_kernel(float* __restrict__ out, int N) {
    __shared__ float sh[KOBJ];
    int k = threadIdx.x;
    float c = g_cnt[k];
    float att = 0.f, rep = 0.f, bet = 0.f, pay = 0.f, no = 0.f;
    if (c > 0.f) {
        att = g_att[k] / (c + FEPS);
        rep = (g_qa[k] * g_rep[k] - g_ro[k]) / ((float)N - c + FEPS);
        bet = 1.0f - g_ba[k];
        pay = g_num[k] / (g_den[k] + FEPS);
        no  = 1.f;
    }
    float vals[5] = { att, rep, bet, pay, no };
    float red[5];
    #pragma unroll
    for (int v = 0; v < 5; v++) {
        sh[k] = vals[v];
        __syncthreads();
        for (int o = 256; o; o >>= 1) {
            if (k < o) sh[k] += sh[k + o];
            __syncthreads();
        }
        red[v] = sh[0];
        __syncthreads();
    }
    if (k == 0) {
        float n_obj  = red[4] + FEPS;
        float lnoise = g_scal[0] / (g_scal[1] + FEPS);
        float lcc    = 0.001f * g_scal[2] / (float)(2 * N);
        out[0] = (red[0] + red[1] + red[2] + red[3]) / n_obj + lnoise + lcc;
    }
}

// ---------------- launch ----------------
extern "C" void kernel_launch(void* const* d_in, const int* in_sizes, int n_in,
                              void* d_out, int out_size) {
    const float* pbeta = (const float*)d_in[0];
    const float* pcc   = (const float*)d_in[1];
    const float* pen   = (const float*)d_in[2];
    const float* ppos  = (const float*)d_in[3];
    const float* ptime = (const float*)d_in[4];
    const float* pid   = (const float*)d_in[5];
    const int*   tidx  = (const int*)  d_in[6];
    const float* ten   = (const float*)d_in[7];
    const float* tpos  = (const float*)d_in[8];
    const float* ttime = (const float*)d_in[9];
    int N = in_sizes[0];
    if (N > MAXN) N = MAXN;

    zero_kernel<<<1, KOBJ>>>();
    passA_kernel<<<(N + 255) / 256, 256>>>(pbeta, pcc, pen, ppos, ptime, pid,
                                           tidx, ten, tpos, ttime, N);
    passB_kernel<<<1, KOBJ>>>();
    passD_kernel<<<(N + 255) / 256, 256>>>(tidx, N);
    passC_kernel<<<1184, 128>>>(N);
    final_kernel<<<1, KOBJ>>>((float*)d_out, N);
}

// round 3
// speedup vs baseline: 1.1462x; 1.1462x over previous
#include <cuda_runtime.h>

#define MAXN 80000
#define KOBJ 512
#define FEPS 1e-9f

// ---------------- scratch (static device globals; no allocation) ----------------
__device__ float4 g_hit[MAXN];                 // x, y, q, x^2+y^2+1e-6
__device__ unsigned long long g_key[KOBJ];     // packed (beta_bits<<32) | ~index
__device__ float g_cnt[KOBJ], g_num[KOBJ], g_den[KOBJ];
__device__ float g_att[KOBJ], g_rep[KOBJ];
__device__ float g_scal[4];                    // noise_beta_sum, noise_cnt, cc_sum

// ---------------- helpers ----------------
__device__ __forceinline__ float asqrtf(float x) {
    float r;
    asm("sqrt.approx.f32 %0, %1;" : "=f"(r) : "f"(x));
    return r;
}

__device__ __forceinline__ float softclipf(float v, float s) {
    float x = v / s;
    if (x > 1.0f) x = __logf(x + 1.0f);
    return x * s;
}

// ---------------- kernel 0: zero accumulators ----------------
__global__ void zero_kernel() {
    int k = threadIdx.x;
    g_key[k] = 0ull;
    g_cnt[k] = 0.f; g_num[k] = 0.f; g_den[k] = 0.f;
    g_att[k] = 0.f; g_rep[k] = 0.f;
    if (k < 4) g_scal[k] = 0.f;
}

// ---------------- kernel 1: per-hit precompute + per-object atomics ----------------
__global__ void passA_kernel(const float* __restrict__ pbeta, const float* __restrict__ pcc,
                             const float* __restrict__ pen,   const float* __restrict__ ppos,
                             const float* __restrict__ ptime, const float* __restrict__ pid,
                             const int*   __restrict__ tidx,  const float* __restrict__ ten,
                             const float* __restrict__ tpos,  const float* __restrict__ ttime,
                             int N)
{
    int i = blockIdx.x * blockDim.x + threadIdx.x;
    float ccs = 0.f, nb = 0.f, nc = 0.f;
    if (i < N) {
        float b = fminf(fmaxf(pbeta[i], 1e-6f), 1.0f - 1e-6f);
        float a = 0.5f * __logf(__fdividef(1.0f + b, 1.0f - b));   // atanh
        float q = a * a + 0.1f;
        float x = pcc[2 * i], y = pcc[2 * i + 1];
        ccs = x * x + y * y;
        g_hit[i] = make_float4(x, y, q, ccs + 1e-6f);
        int k = tidx[i];
        if (k < 0) {
            nb = b; nc = 1.f;
        } else {
            atomicAdd(&g_cnt[k], 1.f);
            unsigned long long key =
                ((unsigned long long)__float_as_uint(b) << 32)
                | (unsigned long long)(0xFFFFFFFFu - (unsigned)i);
            atomicMax(&g_key[k], key);

            float tev = ten[i];
            // energy loss (alt form) + softclip(·, 10)
            float ed = fabsf(tev - pen[i]);
            float el = softclipf(10.0f * __expf(-0.1f * ed * ed) + 0.01f * ed, 10.0f);
            // position loss: huber(sqrt(d2/100 + 0.01), 10), softclip 3
            float dx = tpos[2 * i]     - ppos[2 * i];
            float dy = tpos[2 * i + 1] - ppos[2 * i + 1];
            float d2 = dx * dx + dy * dy;
            float arg = sqrtf(d2 * 0.01f + 0.01f);
            float hub = (arg < 10.0f) ? arg * arg : 100.0f + 20.0f * (arg - 10.0f);
            float pl = softclipf(hub, 3.0f);
            // timing loss: huber(dt, 2), softclip 6
            float dt  = ttime[i] - ptime[i];
            float adt = fabsf(dt);
            float th = (adt < 2.0f) ? dt * dt : 4.0f + 4.0f * (adt - 2.0f);
            float tl = softclipf(th, 6.0f);
            // classification loss: 1e-8 * mean(pred_id^2)
            float cs = 0.f;
            #pragma unroll
            for (int c = 0; c < 6; c++) { float v = pid[6 * i + c]; cs += v * v; }
            float cl = 1e-8f * (cs * (1.0f / 6.0f));

            float payload = el + pl + tl + cl;
            float w  = (tev > 10.0f) ? 1.0f : fmaxf((tev - 0.5f) * (1.0f / 9.5f), 0.0f);
            float pw = b * w;
            atomicAdd(&g_num[k], payload * pw);
            atomicAdd(&g_den[k], pw);
        }
    }
    // warp-reduce the global scalars
    #pragma unroll
    for (int o = 16; o; o >>= 1) {
        ccs += __shfl_down_sync(0xFFFFFFFFu, ccs, o);
        nb  += __shfl_down_sync(0xFFFFFFFFu, nb,  o);
        nc  += __shfl_down_sync(0xFFFFFFFFu, nc,  o);
    }
    if ((threadIdx.x & 31) == 0) {
        if (ccs != 0.f) atomicAdd(&g_scal[2], ccs);
        if (nc  != 0.f) { atomicAdd(&g_scal[0], nb); atomicAdd(&g_scal[1], nc); }
    }
}

// ---------------- kernel 2: fused N x K sweep (repulsion + attraction, own-pair aware) ----------------
__global__ void __launch_bounds__(128) passC_kernel(const int* __restrict__ tidx, int N) {
    int t = threadIdx.x;                       // each thread owns 4 objects
    float mx[4], my[4], c2[4], rep[4], att[4];
    int kk[4];
    #pragma unroll
    for (int j = 0; j < 4; j++) {
        int k = t + 128 * j;
        kk[j] = k;
        rep[j] = 0.f; att[j] = 0.f;
        mx[j] = 0.f; my[j] = 0.f; c2[j] = 0.f;
        if (g_cnt[k] > 0.f) {
            unsigned a = 0xFFFFFFFFu - (unsigned)(g_key[k] & 0xFFFFFFFFull);
            float4 h = g_hit[a];
            mx[j] = -2.f * h.x; my[j] = -2.f * h.y; c2[j] = h.x * h.x + h.y * h.y;
        }
    }

    int per = (N + (int)gridDim.x - 1) / (int)gridDim.x;
    int s = blockIdx.x * per;
    int e = min(N, s + per);

    #pragma unroll 2
    for (int i = s; i < e; ++i) {
        float4 h = __ldg(&g_hit[i]);           // warp-uniform -> L1 broadcast
        int ti = __ldg(&tidx[i]);
        float hx = h.x, hy = h.y, hq = h.z, hw = h.w;
        #pragma unroll
        for (int j = 0; j < 4; j++) {
            float u = fmaf(mx[j], hx, fmaf(my[j], hy, hw)) + c2[j];  // d2 + 1e-6
            float sd = asqrtf(u);
            float relu = fmaxf(fmaf(-sd, hq, hq), 0.0f);             // max(1-sqrt,0)*q (NaN->0)
            bool own = (ti == kk[j]);
            rep[j] += own ? 0.f : relu;
            if (own) att[j] = fmaf(u, hq, att[j]);
        }
    }
    #pragma unroll
    for (int j = 0; j < 4; j++) {
        atomicAdd(&g_rep[kk[j]], rep[j]);
        atomicAdd(&g_att[kk[j]], att[j]);
    }
}

// ---------------- kernel 3: per-object normalization + final reduction ----------------
__global__ void final_kernel(float* __restrict__ out, int N) {
    __shared__ float sh[KOBJ];
    int k = threadIdx.x;
    float c = g_cnt[k];
    float att = 0.f, rep = 0.f, bet = 0.f, pay = 0.f, no = 0.f;
    if (c > 0.f) {
        unsigned long long key = g_key[k];
        unsigned a = 0xFFFFFFFFu - (unsigned)(key & 0xFFFFFFFFull);
        float qa = g_hit[a].z;
        float ba = __uint_as_float((unsigned)(key >> 32));   // clipped beta at alpha
        att = qa * g_att[k] / (c + FEPS);
        rep = qa * g_rep[k] / ((float)N - c + FEPS);
        bet = 1.0f - ba;
        pay = g_num[k] / (g_den[k] + FEPS);
        no  = 1.f;
    }
    float vals[5] = { att, rep, bet, pay, no };
    float red[5];
    #pragma unroll
    for (int v = 0; v < 5; v++) {
        sh[k] = vals[v];
        __syncthreads();
        for (int o = 256; o; o >>= 1) {
            if (k < o) sh[k] += sh[k + o];
            __syncthreads();
        }
        red[v] = sh[0];
        __syncthreads();
    }
    if (k == 0) {
        float n_obj  = red[4] + FEPS;
        float lnoise = g_scal[0] / (g_scal[1] + FEPS);
        float lcc    = 0.001f * g_scal[2] / (float)(2 * N);
        out[0] = (red[0] + red[1] + red[2] + red[3]) / n_obj + lnoise + lcc;
    }
}

// ---------------- launch ----------------
extern "C" void kernel_launch(void* const* d_in, const int* in_sizes, int n_in,
                              void* d_out, int out_size) {
    const float* pbeta = (const float*)d_in[0];
    const float* pcc   = (const float*)d_in[1];
    const float* pen   = (const float*)d_in[2];
    const float* ppos  = (const float*)d_in[3];
    const float* ptime = (const float*)d_in[4];
    const float* pid   = (const float*)d_in[5];
    const int*   tidx  = (const int*)  d_in[6];
    const float* ten   = (const float*)d_in[7];
    const float* tpos  = (const float*)d_in[8];
    const float* ttime = (const float*)d_in[9];
    int N = in_sizes[0];
    if (N > MAXN) N = MAXN;

    zero_kernel<<<1, KOBJ>>>();
    passA_kernel<<<(N + 255) / 256, 256>>>(pbeta, pcc, pen, ppos, ptime, pid,
                                           tidx, ten, tpos, ttime, N);
    passC_kernel<<<1184, 128>>>(tidx, N);
    final_kernel<<<1, KOBJ>>>((float*)d_out, N);
}

// round 4
// speedup vs baseline: 1.1515x; 1.0046x over previous
#include <cuda_runtime.h>

#define MAXN 80000
#define KOBJ 512
#define FEPS 1e-9f

// ---------------- scratch (static device globals; no allocation) ----------------
// NOTE: zero-initialized at module load; final_kernel re-zeros them each run,
// so no separate zero kernel is needed.
__device__ float4 g_hit[MAXN];                 // x, y, q, x^2+y^2+1e-6
__device__ unsigned long long g_key[KOBJ];     // packed (beta_bits<<32) | ~index
__device__ float g_cnt[KOBJ], g_num[KOBJ], g_den[KOBJ];
__device__ float g_att[KOBJ], g_rep[KOBJ];
__device__ float g_scal[4];                    // noise_beta_sum, noise_cnt, cc_sum

// ---------------- helpers ----------------
__device__ __forceinline__ float asqrtf(float x) {
    float r;
    asm("sqrt.approx.f32 %0, %1;" : "=f"(r) : "f"(x));
    return r;
}
__device__ __forceinline__ float softclipf(float v, float s) {
    float x = v / s;
    if (x > 1.0f) x = __logf(x + 1.0f);
    return x * s;
}
// f32x2 packed ops (sm_100+; ptxas never auto-fuses these)
typedef unsigned long long ull;
__device__ __forceinline__ ull pk2(float lo, float hi) {
    ull r; asm("mov.b64 %0, {%1, %2};" : "=l"(r) : "f"(lo), "f"(hi)); return r;
}
__device__ __forceinline__ void upk2(float& lo, float& hi, ull v) {
    asm("mov.b64 {%0, %1}, %2;" : "=f"(lo), "=f"(hi) : "l"(v));
}
__device__ __forceinline__ ull fma2(ull a, ull b, ull c) {
    ull d; asm("fma.rn.f32x2 %0, %1, %2, %3;" : "=l"(d) : "l"(a), "l"(b), "l"(c)); return d;
}
__device__ __forceinline__ ull add2(ull a, ull b) {
    ull d; asm("add.rn.f32x2 %0, %1, %2;" : "=l"(d) : "l"(a), "l"(b)); return d;
}

// ---------------- kernel 1: per-hit precompute + per-object atomics ----------------
__global__ void passA_kernel(const float* __restrict__ pbeta, const float* __restrict__ pcc,
                             const float* __restrict__ pen,   const float* __restrict__ ppos,
                             const float* __restrict__ ptime, const float* __restrict__ pid,
                             const int*   __restrict__ tidx,  const float* __restrict__ ten,
                             const float* __restrict__ tpos,  const float* __restrict__ ttime,
                             int N)
{
    int i = blockIdx.x * blockDim.x + threadIdx.x;
    float ccs = 0.f, nb = 0.f, nc = 0.f;
    if (i < N) {
        float b = fminf(fmaxf(pbeta[i], 1e-6f), 1.0f - 1e-6f);
        float a = 0.5f * __logf(__fdividef(1.0f + b, 1.0f - b));   // atanh
        float q = a * a + 0.1f;
        float x = pcc[2 * i], y = pcc[2 * i + 1];
        ccs = x * x + y * y;
        g_hit[i] = make_float4(x, y, q, ccs + 1e-6f);
        int k = tidx[i];
        if (k < 0) {
            nb = b; nc = 1.f;
        } else {
            atomicAdd(&g_cnt[k], 1.f);
            unsigned long long key =
                ((unsigned long long)__float_as_uint(b) << 32)
                | (unsigned long long)(0xFFFFFFFFu - (unsigned)i);
            atomicMax(&g_key[k], key);

            float tev = ten[i];
            float ed = fabsf(tev - pen[i]);
            float el = softclipf(10.0f * __expf(-0.1f * ed * ed) + 0.01f * ed, 10.0f);
            float dx = tpos[2 * i]     - ppos[2 * i];
            float dy = tpos[2 * i + 1] - ppos[2 * i + 1];
            float d2 = dx * dx + dy * dy;
            float arg = sqrtf(d2 * 0.01f + 0.01f);
            float hub = (arg < 10.0f) ? arg * arg : 100.0f + 20.0f * (arg - 10.0f);
            float pl = softclipf(hub, 3.0f);
            float dt  = ttime[i] - ptime[i];
            float adt = fabsf(dt);
            float th = (adt < 2.0f) ? dt * dt : 4.0f + 4.0f * (adt - 2.0f);
            float tl = softclipf(th, 6.0f);
            float cs = 0.f;
            #pragma unroll
            for (int c = 0; c < 6; c++) { float v = pid[6 * i + c]; cs += v * v; }
            float cl = 1e-8f * (cs * (1.0f / 6.0f));

            float payload = el + pl + tl + cl;
            float w  = (tev > 10.0f) ? 1.0f : fmaxf((tev - 0.5f) * (1.0f / 9.5f), 0.0f);
            float pw = b * w;
            atomicAdd(&g_num[k], payload * pw);
            atomicAdd(&g_den[k], pw);
        }
    }
    #pragma unroll
    for (int o = 16; o; o >>= 1) {
        ccs += __shfl_down_sync(0xFFFFFFFFu, ccs, o);
        nb  += __shfl_down_sync(0xFFFFFFFFu, nb,  o);
        nc  += __shfl_down_sync(0xFFFFFFFFu, nc,  o);
    }
    if ((threadIdx.x & 31) == 0) {
        if (ccs != 0.f) atomicAdd(&g_scal[2], ccs);
        if (nc  != 0.f) { atomicAdd(&g_scal[0], nb); atomicAdd(&g_scal[1], nc); }
    }
}

// ---------------- kernel 2: fused N x K sweep, f32x2 packed ----------------
__global__ void __launch_bounds__(128) passC_kernel(const int* __restrict__ tidx, int N) {
    int t = threadIdx.x;                       // thread owns k = t, t+128, t+256, t+384
    float mxs[4], mys[4], css[4];
    #pragma unroll
    for (int j = 0; j < 4; j++) {
        int k = t + 128 * j;
        mxs[j] = 0.f; mys[j] = 0.f; css[j] = 0.f;
        if (g_cnt[k] > 0.f) {
            unsigned a = 0xFFFFFFFFu - (unsigned)(g_key[k] & 0xFFFFFFFFull);
            float4 h = g_hit[a];
            mxs[j] = -2.f * h.x; mys[j] = -2.f * h.y; css[j] = h.x * h.x + h.y * h.y;
        }
    }
    ull mxp[2] = { pk2(mxs[0], mxs[1]), pk2(mxs[2], mxs[3]) };
    ull myp[2] = { pk2(mys[0], mys[1]), pk2(mys[2], mys[3]) };
    ull cp [2] = { pk2(css[0], css[1]), pk2(css[2], css[3]) };
    ull racc[2] = { pk2(0.f, 0.f), pk2(0.f, 0.f) };
    float att[4]  = {0.f, 0.f, 0.f, 0.f};
    float rsub[4] = {0.f, 0.f, 0.f, 0.f};

    int per = (N + (int)gridDim.x - 1) / (int)gridDim.x;
    int s = blockIdx.x * per;
    int e = min(N, s + per);

    for (int i = s; i < e; ++i) {
        float4 h = __ldg(&g_hit[i]);           // warp-uniform -> L1 broadcast
        int ti = __ldg(&tidx[i]);
        ull hx2 = pk2(h.x, h.x), hy2 = pk2(h.y, h.y), hw2 = pk2(h.w, h.w);
        ull q2  = pk2(h.z, h.z), nq2 = pk2(-h.z, -h.z);
        float u[4], m[4];
        #pragma unroll
        for (int p = 0; p < 2; p++) {
            ull w  = add2(hw2, cp[p]);
            ull v  = fma2(myp[p], hy2, w);
            ull uu = fma2(mxp[p], hx2, v);          // d2 + 1e-6, two k's
            float u0, u1; upk2(u0, u1, uu);
            float sd0 = (u0 < 1.0f) ? asqrtf(u0) : 1.0f;   // sd=1 -> relu term 0
            float sd1 = (u1 < 1.0f) ? asqrtf(u1) : 1.0f;
            ull rel = fma2(pk2(sd0, sd1), nq2, q2);        // q - q*sd
            float r0, r1; upk2(r0, r1, rel);
            m[2*p]   = fmaxf(r0, 0.0f);                    // NaN -> 0
            m[2*p+1] = fmaxf(r1, 0.0f);
            racc[p] = add2(racc[p], pk2(m[2*p], m[2*p+1]));
            u[2*p] = u0; u[2*p+1] = u1;
        }
        // own-object pair: rare (<=1 lane per warp-iter)
        if (ti >= 0 && (ti & 127) == t) {
            int j = ti >> 7;
            #pragma unroll
            for (int j2 = 0; j2 < 4; j2++)
                if (j == j2) {
                    att[j2]  = fmaf(u[j2], h.z, att[j2]);  // attractive d2*q (qa applied later)
                    rsub[j2] += m[j2];                      // exclude own term from repulsion
                }
        }
    }
    float rr[4];
    upk2(rr[0], rr[1], racc[0]);
    upk2(rr[2], rr[3], racc[1]);
    #pragma unroll
    for (int j = 0; j < 4; j++) {
        atomicAdd(&g_rep[t + 128 * j], rr[j] - rsub[j]);
        atomicAdd(&g_att[t + 128 * j], att[j]);
    }
}

// ---------------- kernel 3: normalize + reduce + reset accumulators ----------------
__global__ void final_kernel(float* __restrict__ out, int N) {
    __shared__ float sh[16][5];
    int k = threadIdx.x;
    int lane = k & 31, wid = k >> 5;

    float c = g_cnt[k];
    float v0 = 0.f, v1 = 0.f, v2 = 0.f, v3 = 0.f, v4 = 0.f;
    if (c > 0.f) {
        unsigned long long key = g_key[k];
        unsigned a = 0xFFFFFFFFu - (unsigned)(key & 0xFFFFFFFFull);
        float qa = g_hit[a].z;
        float ba = __uint_as_float((unsigned)(key >> 32));
        v0 = qa * g_att[k] / (c + FEPS);
        v1 = qa * g_rep[k] / ((float)N - c + FEPS);
        v2 = 1.0f - ba;
        v3 = g_num[k] / (g_den[k] + FEPS);
        v4 = 1.f;
    }
    // reset accumulators for the next graph replay (reads above are done)
    g_cnt[k] = 0.f; g_key[k] = 0ull; g_num[k] = 0.f; g_den[k] = 0.f;
    g_att[k] = 0.f; g_rep[k] = 0.f;

    #pragma unroll
    for (int o = 16; o; o >>= 1) {
        v0 += __shfl_down_sync(0xFFFFFFFFu, v0, o);
        v1 += __shfl_down_sync(0xFFFFFFFFu, v1, o);
        v2 += __shfl_down_sync(0xFFFFFFFFu, v2, o);
        v3 += __shfl_down_sync(0xFFFFFFFFu, v3, o);
        v4 += __shfl_down_sync(0xFFFFFFFFu, v4, o);
    }
    if (lane == 0) {
        sh[wid][0] = v0; sh[wid][1] = v1; sh[wid][2] = v2;
        sh[wid][3] = v3; sh[wid][4] = v4;
    }
    __syncthreads();
    if (k < 32) {
        float a0 = (k < 16) ? sh[k][0] : 0.f;
        float a1 = (k < 16) ? sh[k][1] : 0.f;
        float a2 = (k < 16) ? sh[k][2] : 0.f;
        float a3 = (k < 16) ? sh[k][3] : 0.f;
        float a4 = (k < 16) ? sh[k][4] : 0.f;
        #pragma unroll
        for (int o = 8; o; o >>= 1) {
            a0 += __shfl_down_sync(0xFFFFFFFFu, a0, o);
            a1 += __shfl_down_sync(0xFFFFFFFFu, a1, o);
            a2 += __shfl_down_sync(0xFFFFFFFFu, a2, o);
            a3 += __shfl_down_sync(0xFFFFFFFFu, a3, o);
            a4 += __shfl_down_sync(0xFFFFFFFFu, a4, o);
        }
        if (k == 0) {
            float n_obj  = a4 + FEPS;
            float lnoise = g_scal[0] / (g_scal[1] + FEPS);
            float lcc    = 0.001f * g_scal[2] / (float)(2 * N);
            out[0] = (a0 + a1 + a2 + a3) / n_obj + lnoise + lcc;
            g_scal[0] = 0.f; g_scal[1] = 0.f; g_scal[2] = 0.f; g_scal[3] = 0.f;
        }
    }
}

// ---------------- launch ----------------
extern "C" void kernel_launch(void* const* d_in, const int* in_sizes, int n_in,
                              void* d_out, int out_size) {
    const float* pbeta = (const float*)d_in[0];
    const float* pcc   = (const float*)d_in[1];
    const float* pen   = (const float*)d_in[2];
    const float* ppos  = (const float*)d_in[3];
    const float* ptime = (const float*)d_in[4];
    const float* pid   = (const float*)d_in[5];
    const int*   tidx  = (const int*)  d_in[6];
    const float* ten   = (const float*)d_in[7];
    const float* tpos  = (const float*)d_in[8];
    const float* ttime = (const float*)d_in[9];
    int N = in_sizes[0];
    if (N > MAXN) N = MAXN;

    passA_kernel<<<(N + 255) / 256, 256>>>(pbeta, pcc, pen, ppos, ptime, pid,
                                           tidx, ten, tpos, ttime, N);
    passC_kernel<<<1184, 128>>>(tidx, N);
    final_kernel<<<1, KOBJ>>>((float*)d_out, N);
}

// round 6
// speedup vs baseline: 1.3416x; 1.1651x over previous
#include <cuda_runtime.h>

#define MAXN 80000
#define KOBJ 512
#define FEPS 1e-9f

// ---------------- scratch (static device globals; no allocation) ----------------
// Zero-initialized at module load; final_kernel re-zeros each run (graph-replay safe).
__device__ float4 g_hit[MAXN];                 // x, y, q, x^2+y^2+1e-6
__device__ unsigned long long g_key[KOBJ];     // packed (beta_bits<<32) | ~index
__device__ float g_cnt[KOBJ], g_num[KOBJ], g_den[KOBJ];
__device__ float g_att[KOBJ], g_rep[KOBJ];
__device__ float g_scal[4];                    // noise_beta_sum, noise_cnt, cc_sum

// ---------------- helpers ----------------
__device__ __forceinline__ float asqrtf(float x) {
    float r;
    asm("sqrt.approx.f32 %0, %1;" : "=f"(r) : "f"(x));
    return r;
}
__device__ __forceinline__ float softclipf(float v, float s) {
    float x = v / s;
    if (x > 1.0f) x = __logf(x + 1.0f);
    return x * s;
}
// f32x2 packed ops (sm_100+)
typedef unsigned long long ull;
__device__ __forceinline__ ull pk2(float lo, float hi) {
    ull r; asm("mov.b64 %0, {%1, %2};" : "=l"(r) : "f"(lo), "f"(hi)); return r;
}
__device__ __forceinline__ void upk2(float& lo, float& hi, ull v) {
    asm("mov.b64 {%0, %1}, %2;" : "=f"(lo), "=f"(hi) : "l"(v));
}
__device__ __forceinline__ ull fma2(ull a, ull b, ull c) {
    ull d; asm("fma.rn.f32x2 %0, %1, %2, %3;" : "=l"(d) : "l"(a), "l"(b), "l"(c)); return d;
}
__device__ __forceinline__ ull add2(ull a, ull b) {
    ull d; asm("add.rn.f32x2 %0, %1, %2;" : "=l"(d) : "l"(a), "l"(b)); return d;
}

// ---------------- kernel 1: per-hit precompute + per-object atomics ----------------
// ALL loads hoisted unconditionally -> single batched DRAM round trip (MLP ~12).
__global__ void passA_kernel(const float* __restrict__ pbeta, const float* __restrict__ pcc,
                             const float* __restrict__ pen,   const float* __restrict__ ppos,
                             const float* __restrict__ ptime, const float* __restrict__ pid,
                             const int*   __restrict__ tidx,  const float* __restrict__ ten,
                             const float* __restrict__ tpos,  const float* __restrict__ ttime,
                             int N)
{
    int i = blockIdx.x * blockDim.x + threadIdx.x;
    float ccs = 0.f, nb = 0.f, nc = 0.f;
    if (i < N) {
        // --- hoisted loads (all independent, issue together) ---
        float  bref = pbeta[i];
        float2 cc   = ((const float2*)pcc)[i];
        float  pe   = pen[i];
        float2 pp   = ((const float2*)ppos)[i];
        float  pt   = ptime[i];
        int    k    = tidx[i];
        float  tev  = ten[i];
        float2 tp   = ((const float2*)tpos)[i];
        float  tt   = ttime[i];
        const float2* pid2 = (const float2*)pid;
        float2 c0 = pid2[3 * i], c1 = pid2[3 * i + 1], c2v = pid2[3 * i + 2];

        // --- per-hit precompute ---
        float b = fminf(fmaxf(bref, 1e-6f), 1.0f - 1e-6f);
        float a = 0.5f * __logf(__fdividef(1.0f + b, 1.0f - b));   // atanh
        float q = a * a + 0.1f;
        ccs = cc.x * cc.x + cc.y * cc.y;
        g_hit[i] = make_float4(cc.x, cc.y, q, ccs + 1e-6f);

        // --- payload (computed unconditionally; cheap, avoids divergence) ---
        float ed = fabsf(tev - pe);
        float el = softclipf(10.0f * __expf(-0.1f * ed * ed) + 0.01f * ed, 10.0f);
        float dx = tp.x - pp.x, dy = tp.y - pp.y;
        float d2 = dx * dx + dy * dy;
        float arg = asqrtf(d2 * 0.01f + 0.01f);
        float hub = (arg < 10.0f) ? arg * arg : 100.0f + 20.0f * (arg - 10.0f);
        float pl = softclipf(hub, 3.0f);
        float dt  = tt - pt;
        float adt = fabsf(dt);
        float th = (adt < 2.0f) ? dt * dt : 4.0f + 4.0f * (adt - 2.0f);
        float tl = softclipf(th, 6.0f);
        float cs = c0.x * c0.x + c0.y * c0.y + c1.x * c1.x + c1.y * c1.y
                 + c2v.x * c2v.x + c2v.y * c2v.y;
        float cl = 1e-8f * (cs * (1.0f / 6.0f));
        float payload = el + pl + tl + cl;
        float w  = (tev > 10.0f) ? 1.0f : fmaxf((tev - 0.5f) * (1.0f / 9.5f), 0.0f);
        float pw = b * w;

        if (k < 0) {
            nb = b; nc = 1.f;
        } else {
            atomicAdd(&g_cnt[k], 1.f);
            unsigned long long key =
                ((unsigned long long)__float_as_uint(b) << 32)
                | (unsigned long long)(0xFFFFFFFFu - (unsigned)i);
            atomicMax(&g_key[k], key);
            atomicAdd(&g_num[k], payload * pw);
            atomicAdd(&g_den[k], pw);
        }
    }
    #pragma unroll
    for (int o = 16; o; o >>= 1) {
        ccs += __shfl_down_sync(0xFFFFFFFFu, ccs, o);
        nb  += __shfl_down_sync(0xFFFFFFFFu, nb,  o);
        nc  += __shfl_down_sync(0xFFFFFFFFu, nc,  o);
    }
    if ((threadIdx.x & 31) == 0) {
        if (ccs != 0.f) atomicAdd(&g_scal[2], ccs);
        if (nc  != 0.f) { atomicAdd(&g_scal[0], nb); atomicAdd(&g_scal[1], nc); }
    }
}

// ---------------- kernel 2: fused N x K sweep, hits packed pairwise in f32x2 ----------------
__global__ void __launch_bounds__(128) passC_kernel(const int* __restrict__ tidx, int N) {
    int t = threadIdx.x;                       // thread owns k = t, t+128, t+256, t+384
    ull mx2[4], my2[4], c22[4];                // object constants broadcast-packed ONCE
    #pragma unroll
    for (int j = 0; j < 4; j++) {
        int k = t + 128 * j;
        float mx = 0.f, my = 0.f, c2 = 0.f;
        if (g_cnt[k] > 0.f) {
            unsigned a = 0xFFFFFFFFu - (unsigned)(g_key[k] & 0xFFFFFFFFull);
            float4 h = g_hit[a];
            mx = -2.f * h.x; my = -2.f * h.y; c2 = h.x * h.x + h.y * h.y;
        }
        mx2[j] = pk2(mx, mx); my2[j] = pk2(my, my); c22[j] = pk2(c2, c2);
    }
    float rep[4] = {0.f, 0.f, 0.f, 0.f};
    float att[4] = {0.f, 0.f, 0.f, 0.f};

    int per = (N + (int)gridDim.x - 1) / (int)gridDim.x;
    int s = blockIdx.x * per;
    int e = min(N, s + per);

    int i = s;
    for (; i + 1 < e; i += 2) {
        float4 h0 = __ldg(&g_hit[i]);
        float4 h1 = __ldg(&g_hit[i + 1]);
        int ti0 = __ldg(&tidx[i]);
        int ti1 = __ldg(&tidx[i + 1]);
        ull hx = pk2(h0.x, h1.x), hy = pk2(h0.y, h1.y), hw = pk2(h0.w, h1.w);
        float ua[8];
        #pragma unroll
        for (int j = 0; j < 4; j++) {
            ull u2 = fma2(mx2[j], hx, fma2(my2[j], hy, add2(hw, c22[j])));  // d2+1e-6 for 2 hits
            float u0, u1; upk2(u0, u1, u2);
            float r0 = fmaxf(fmaf(-asqrtf(u0), h0.z, h0.z), 0.0f);   // max(q - q*sqrt, 0); NaN->0
            float r1 = fmaxf(fmaf(-asqrtf(u1), h1.z, h1.z), 0.0f);
            rep[j] += r0;
            rep[j] += r1;
            ua[2 * j] = u0; ua[2 * j + 1] = u1;
        }
        // own-object pairs: rare (taken by <=1 lane, ~50% of warp-iters)
        if (ti0 >= 0 && (ti0 & 127) == t) {
            int j = ti0 >> 7;
            #pragma unroll
            for (int j2 = 0; j2 < 4; j2++)
                if (j2 == j) {
                    float u = ua[2 * j2];
                    att[j2] = fmaf(u, h0.z, att[j2]);
                    rep[j2] -= fmaxf(fmaf(-asqrtf(u), h0.z, h0.z), 0.0f);  // bit-identical to packed term
                }
        }
        if (ti1 >= 0 && (ti1 & 127) == t) {
            int j = ti1 >> 7;
            #pragma unroll
            for (int j2 = 0; j2 < 4; j2++)
                if (j2 == j) {
                    float u = ua[2 * j2 + 1];
                    att[j2] = fmaf(u, h1.z, att[j2]);
                    rep[j2] -= fmaxf(fmaf(-asqrtf(u), h1.z, h1.z), 0.0f);
                }
        }
    }
    if (i < e) {                                // odd remainder hit
        float4 h0 = __ldg(&g_hit[i]);
        int ti0 = __ldg(&tidx[i]);
        #pragma unroll
        for (int j = 0; j < 4; j++) {
            float mxl, mxh; upk2(mxl, mxh, mx2[j]); (void)mxh;
            float myl, myh; upk2(myl, myh, my2[j]); (void)myh;
            float cl,  ch;  upk2(cl,  ch,  c22[j]); (void)ch;
            float u = fmaf(mxl, h0.x, fmaf(myl, h0.y, h0.w)) + cl;
            float r = fmaxf(fmaf(-asqrtf(u), h0.z, h0.z), 0.0f);
            bool own = (ti0 == t + 128 * j);
            rep[j] += own ? 0.f : r;
            if (own) att[j] = fmaf(u, h0.z, att[j]);
        }
    }
    #pragma unroll
    for (int j = 0; j < 4; j++) {
        atomicAdd(&g_rep[t + 128 * j], rep[j]);
        atomicAdd(&g_att[t + 128 * j], att[j]);
    }
}

// ---------------- kernel 3: normalize + reduce + reset accumulators ----------------
__global__ void final_kernel(float* __restrict__ out, int N) {
    __shared__ float sh[16][5];
    int k = threadIdx.x;
    int lane = k & 31, wid = k >> 5;

    float c = g_cnt[k];
    float v0 = 0.f, v1 = 0.f, v2 = 0.f, v3 = 0.f, v4 = 0.f;
    if (c > 0.f) {
        unsigned long long key = g_key[k];
        unsigned a = 0xFFFFFFFFu - (unsigned)(key & 0xFFFFFFFFull);
        float qa = g_hit[a].z;
        float ba = __uint_as_float((unsigned)(key >> 32));
        v0 = qa * g_att[k] / (c + FEPS);
        v1 = qa * g_rep[k] / ((float)N - c + FEPS);
        v2 = 1.0f - ba;
        v3 = g_num[k] / (g_den[k] + FEPS);
        v4 = 1.f;
    }
    // reset accumulators for the next graph replay
    g_cnt[k] = 0.f; g_key[k] = 0ull; g_num[k] = 0.f; g_den[k] = 0.f;
    g_att[k] = 0.f; g_rep[k] = 0.f;

    #pragma unroll
    for (int o = 16; o; o >>= 1) {
        v0 += __shfl_down_sync(0xFFFFFFFFu, v0, o);
        v1 += __shfl_down_sync(0xFFFFFFFFu, v1, o);
        v2 += __shfl_down_sync(0xFFFFFFFFu, v2, o);
        v3 += __shfl_down_sync(0xFFFFFFFFu, v3, o);
        v4 += __shfl_down_sync(0xFFFFFFFFu, v4, o);
    }
    if (lane == 0) {
        sh[wid][0] = v0; sh[wid][1] = v1; sh[wid][2] = v2;
        sh[wid][3] = v3; sh[wid][4] = v4;
    }
    __syncthreads();
    if (k < 32) {
        float a0 = (k < 16) ? sh[k][0] : 0.f;
        float a1 = (k < 16) ? sh[k][1] : 0.f;
        float a2 = (k < 16) ? sh[k][2] : 0.f;
        float a3 = (k < 16) ? sh[k][3] : 0.f;
        float a4 = (k < 16) ? sh[k][4] : 0.f;
        #pragma unroll
        for (int o = 8; o; o >>= 1) {
            a0 += __shfl_down_sync(0xFFFFFFFFu, a0, o);
            a1 += __shfl_down_sync(0xFFFFFFFFu, a1, o);
            a2 += __shfl_down_sync(0xFFFFFFFFu, a2, o);
            a3 += __shfl_down_sync(0xFFFFFFFFu, a3, o);
            a4 += __shfl_down_sync(0xFFFFFFFFu, a4, o);
        }
        if (k == 0) {
            float n_obj  = a4 + FEPS;
            float lnoise = g_scal[0] / (g_scal[1] + FEPS);
            float lcc    = 0.001f * g_scal[2] / (float)(2 * N);
            out[0] = (a0 + a1 + a2 + a3) / n_obj + lnoise + lcc;
            g_scal[0] = 0.f; g_scal[1] = 0.f; g_scal[2] = 0.f; g_scal[3] = 0.f;
        }
    }
}

// ---------------- launch ----------------
extern "C" void kernel_launch(void* const* d_in, const int* in_sizes, int n_in,
                              void* d_out, int out_size) {
    const float* pbeta = (const float*)d_in[0];
    const float* pcc   = (const float*)d_in[1];
    const float* pen   = (const float*)d_in[2];
    const float* ppos  = (const float*)d_in[3];
    const float* ptime = (const float*)d_in[4];
    const float* pid   = (const float*)d_in[5];
    const int*   tidx  = (const int*)  d_in[6];
    const float* ten   = (const float*)d_in[7];
    const float* tpos  = (const float*)d_in[8];
    const float* ttime = (const float*)d_in[9];
    int N = in_sizes[0];
    if (N > MAXN) N = MAXN;

    passA_kernel<<<(N + 255) / 256, 256>>>(pbeta, pcc, pen, ppos, ptime, pid,
                                           tidx, ten, tpos, ttime, N);
    passC_kernel<<<1184, 128>>>(tidx, N);
    final_kernel<<<1, KOBJ>>>((float*)d_out, N);
}